// round 3
// baseline (speedup 1.0000x reference)
#include <cuda_runtime.h>
#include <cuda_bf16.h>
#include <math.h>

// Problem constants
constexpr int B_ = 64;
constexpr int T_ = 256;
constexpr int D_ = 512;
constexpr int H_ = 1024;
constexpr int G4 = 4 * H_;         // 4096
constexpr int BH = B_ * H_;        // 65536

// Scratch (device globals — allocation-free per harness rules)
__device__ float g_xw[(size_t)B_ * T_ * G4];        // (B*T, 4H)  268 MB
__device__ float g_h[BH];
__device__ float g_c[BH];
__device__ float g_ys1[(size_t)B_ * T_ * H_];       // (B*T, H)   67 MB
__device__ float g_ys2[(size_t)B_ * T_ * H_];       // (B*T, H)
__device__ float g_z1[(size_t)B_ * T_ * (H_ / 2)];  // (B, T*512)
__device__ float g_z2[B_ * 36];

// -------------------------- software grid barrier --------------------------
__device__ unsigned g_bar_count = 0;
__device__ volatile unsigned g_bar_gen = 0;

__device__ __forceinline__ void grid_barrier(unsigned nblocks)
{
    __syncthreads();
    if (threadIdx.x == 0) {
        __threadfence();                       // make h/c stores visible
        unsigned gen = g_bar_gen;
        if (atomicAdd(&g_bar_count, 1u) == nblocks - 1u) {
            g_bar_count = 0;
            __threadfence();
            g_bar_gen = gen + 1u;
        } else {
            while (g_bar_gen == gen) { }
        }
    }
    __syncthreads();
}

__device__ __forceinline__ float sigmoidf(float x) { return 1.f / (1.f + expf(-x)); }

// ---------------------------------------------------------------------------
// Persistent LSTM layer: 128 CTAs x 256 threads, all resident.
// CTA owns 8 h-columns (j0..j0+7) across all 4 gates (a 64x32 gate tile).
// Per step: SMEM-tiled GEMM tile of h @ U, add xw[t], cell update, 1 barrier.
// xw rows are indexed (b*T + t).  At t==0, h/c come from h0/c0 pointers.
// ---------------------------------------------------------------------------
__global__ void __launch_bounds__(256) lstm_layer(
    const float* __restrict__ U,    // (H, 4H)
    const float* __restrict__ xw,   // (B*T, 4H)
    const float* __restrict__ h0,   // (B, H) initial hidden
    const float* __restrict__ c0,   // (B, H) initial cell
    float* __restrict__ h,          // (B, H) working/final hidden
    float* __restrict__ c,          // (B, H) working/final cell
    float* __restrict__ ys)         // (B*T, H)
{
    const unsigned nblocks = gridDim.x;     // 128
    const int j0 = blockIdx.x * 8;          // 8 j-columns per CTA
    const int tid = threadIdx.x;
    const int ty = tid >> 4;                // 0..15 -> 4 rows each
    const int tx = tid & 15;                // 0..15 -> 2 cols each

    __shared__ float As[16][64];
    __shared__ float Bs[16][32];
    __shared__ float Cs[64][33];            // padded

    for (int t = 0; t < T_; t++) {
        const float* hsrc = (t == 0) ? h0 : h;

        float acc[4][2];
#pragma unroll
        for (int r = 0; r < 4; r++) { acc[r][0] = 0.f; acc[r][1] = 0.f; }

        for (int k0 = 0; k0 < H_; k0 += 16) {
            // A tile: 64 rows x 16 k (one float4 per thread), L2-coherent load
            {
                int r = tid >> 2;                 // 0..63
                int cc = (tid & 3) * 4;           // 0,4,8,12
                float4 av = __ldcg(reinterpret_cast<const float4*>(
                    hsrc + (size_t)r * H_ + k0 + cc));
                As[cc + 0][r] = av.x;
                As[cc + 1][r] = av.y;
                As[cc + 2][r] = av.z;
                As[cc + 3][r] = av.w;
            }
            // B tile: 16 k x 32 cols; col cc -> U column (cc/8)*H + j0 + cc%8
            {
#pragma unroll
                for (int e = 0; e < 2; e++) {
                    int v = tid * 2 + e;
                    int kk = v >> 5;
                    int cc = v & 31;
                    int col = (cc >> 3) * H_ + j0 + (cc & 7);
                    Bs[kk][cc] = U[(size_t)(k0 + kk) * G4 + col];
                }
            }
            __syncthreads();
#pragma unroll
            for (int k = 0; k < 16; k++) {
                const float4 a = *reinterpret_cast<const float4*>(&As[k][ty * 4]);
                const float b0 = Bs[k][tx * 2 + 0];
                const float b1 = Bs[k][tx * 2 + 1];
                acc[0][0] = fmaf(a.x, b0, acc[0][0]);
                acc[1][0] = fmaf(a.y, b0, acc[1][0]);
                acc[2][0] = fmaf(a.z, b0, acc[2][0]);
                acc[3][0] = fmaf(a.w, b0, acc[3][0]);
                acc[0][1] = fmaf(a.x, b1, acc[0][1]);
                acc[1][1] = fmaf(a.y, b1, acc[1][1]);
                acc[2][1] = fmaf(a.z, b1, acc[2][1]);
                acc[3][1] = fmaf(a.w, b1, acc[3][1]);
            }
            __syncthreads();
        }

        // stage tile in SMEM so cell update can use a (b,j)-aligned mapping
#pragma unroll
        for (int r = 0; r < 4; r++) {
            Cs[ty * 4 + r][tx * 2 + 0] = acc[r][0];
            Cs[ty * 4 + r][tx * 2 + 1] = acc[r][1];
        }
        __syncthreads();

        // cell update: 512 cells (64 b x 8 j), 2 per thread
#pragma unroll
        for (int e = 0; e < 2; e++) {
            int cell = tid * 2 + e;
            int b = cell >> 3;
            int jj = cell & 7;
            int col = j0 + jj;
            size_t xrow = ((size_t)b * T_ + t) * G4;
            float iv = Cs[b][0 * 8 + jj] + xw[xrow + 0 * H_ + col];
            float fv = Cs[b][1 * 8 + jj] + xw[xrow + 1 * H_ + col];
            float gv = Cs[b][2 * 8 + jj] + xw[xrow + 2 * H_ + col];
            float ov = Cs[b][3 * 8 + jj] + xw[xrow + 3 * H_ + col];
            int idx = b * H_ + col;
            float cprev = (t == 0) ? c0[idx] : c[idx];
            float cn = sigmoidf(fv) * cprev + sigmoidf(iv) * tanhf(gv);
            float hn = sigmoidf(ov) * tanhf(cn);
            c[idx] = cn;
            h[idx] = hn;
            ys[((size_t)b * T_ + t) * H_ + col] = hn;
        }
        __syncthreads();          // Cs reuse safety for next iteration
        grid_barrier(nblocks);    // h fully updated before next step's reads
    }
}

// ---------------------------------------------------------------------------
// Generic fp32 tiled SGEMM: C = A(MxK) @ B(KxN) + bias(N)
// ---------------------------------------------------------------------------
template <int BM, int BN, int BK>
__global__ void sgemm(const float* __restrict__ A, const float* __restrict__ Bm,
                      const float* __restrict__ bias, float* __restrict__ C,
                      int M, int N, int K)
{
    constexpr int TM = BM / 16;
    constexpr int TN = BN / 16;
    __shared__ float As[BK][BM];
    __shared__ float Bs[BK][BN];

    const int bm = blockIdx.y * BM;
    const int bn = blockIdx.x * BN;
    const int tid = threadIdx.x;
    const int tx = tid & 15;
    const int ty = tid >> 4;

    float acc[TM][TN];
#pragma unroll
    for (int i = 0; i < TM; i++)
#pragma unroll
        for (int j = 0; j < TN; j++) acc[i][j] = 0.f;

    for (int k0 = 0; k0 < K; k0 += BK) {
        for (int v = tid; v < BM * BK / 4; v += 256) {
            int r = v / (BK / 4);
            int cc = (v % (BK / 4)) * 4;
            float4 av = *(const float4*)(A + (size_t)(bm + r) * K + k0 + cc);
            As[cc + 0][r] = av.x;
            As[cc + 1][r] = av.y;
            As[cc + 2][r] = av.z;
            As[cc + 3][r] = av.w;
        }
        for (int v = tid; v < BK * BN / 4; v += 256) {
            int r = v / (BN / 4);
            int cc = (v % (BN / 4)) * 4;
            *(float4*)(&Bs[r][cc]) = *(const float4*)(Bm + (size_t)(k0 + r) * N + bn + cc);
        }
        __syncthreads();
#pragma unroll
        for (int k = 0; k < BK; k++) {
            float ar[TM], br[TN];
#pragma unroll
            for (int i = 0; i < TM; i++) ar[i] = As[k][ty * TM + i];
#pragma unroll
            for (int j = 0; j < TN; j++) br[j] = Bs[k][tx * TN + j];
#pragma unroll
            for (int i = 0; i < TM; i++)
#pragma unroll
                for (int j = 0; j < TN; j++) acc[i][j] = fmaf(ar[i], br[j], acc[i][j]);
        }
        __syncthreads();
    }

#pragma unroll
    for (int i = 0; i < TM; i++) {
        int row = bm + ty * TM + i;
#pragma unroll
        for (int j = 0; j < TN; j++) {
            int col = bn + tx * TN + j;
            float v = acc[i][j];
            if (bias) v += bias[col];
            C[(size_t)row * N + col] = v;
        }
    }
}

// fc2: out(64,36) = A(64,131072) @ W(131072,36) + bias. One block per row m.
__global__ void fc2_kernel(const float* __restrict__ A, const float* __restrict__ W,
                           const float* __restrict__ bias, float* __restrict__ out)
{
    constexpr int K = T_ * (H_ / 2);  // 131072
    int m = blockIdx.x;
    int tid = threadIdx.x;  // 256
    float acc[36];
#pragma unroll
    for (int n = 0; n < 36; n++) acc[n] = 0.f;
    const float* arow = A + (size_t)m * K;
    for (int k = tid; k < K; k += 256) {
        float a = arow[k];
        const float* wr = W + (size_t)k * 36;
#pragma unroll
        for (int n = 0; n < 36; n++) acc[n] = fmaf(a, wr[n], acc[n]);
    }
    __shared__ float red[256];
    for (int n = 0; n < 36; n++) {
        red[tid] = acc[n];
        __syncthreads();
        for (int s = 128; s > 0; s >>= 1) {
            if (tid < s) red[tid] += red[tid + s];
            __syncthreads();
        }
        if (tid == 0) out[m * 36 + n] = red[0] + bias[n];
        __syncthreads();
    }
}

// fc3 (36->6) + fc4 (6->6) + relu; one thread per batch row
__global__ void fc34_kernel(const float* __restrict__ z2,
                            const float* __restrict__ w3, const float* __restrict__ b3,
                            const float* __restrict__ w4, const float* __restrict__ b4,
                            float* __restrict__ out)
{
    int m = threadIdx.x;
    if (m >= B_) return;
    float t3[6];
#pragma unroll
    for (int n = 0; n < 6; n++) {
        float s = b3[n];
        for (int k = 0; k < 36; k++) s = fmaf(z2[m * 36 + k], w3[k * 6 + n], s);
        t3[n] = s;
    }
#pragma unroll
    for (int n = 0; n < 6; n++) {
        float s = b4[n];
#pragma unroll
        for (int k = 0; k < 6; k++) s = fmaf(t3[k], w4[k * 6 + n], s);
        out[m * 6 + n] = fmaxf(s, 0.f);
    }
}

// ---------------------------------------------------------------------------
extern "C" void kernel_launch(void* const* d_in, const int* in_sizes, int n_in,
                              void* d_out, int out_size)
{
    const float* x     = (const float*)d_in[0];   // (B,T,D) == (B*T, D) rows b*T+t
    const float* h0    = (const float*)d_in[1];
    const float* c0    = (const float*)d_in[2];
    const float* W1    = (const float*)d_in[3];
    const float* U1    = (const float*)d_in[4];
    const float* b1    = (const float*)d_in[5];
    const float* W2    = (const float*)d_in[6];
    const float* U2    = (const float*)d_in[7];
    const float* b2    = (const float*)d_in[8];
    const float* fc1_w = (const float*)d_in[9];
    const float* fc1_b = (const float*)d_in[10];
    const float* fc2_w = (const float*)d_in[11];
    const float* fc2_b = (const float*)d_in[12];
    const float* fc3_w = (const float*)d_in[13];
    const float* fc3_b = (const float*)d_in[14];
    const float* fc4_w = (const float*)d_in[15];
    const float* fc4_b = (const float*)d_in[16];
    float* out = (float*)d_out;

    float *xw, *h, *c, *ys1, *ys2, *z1, *z2;
    cudaGetSymbolAddress((void**)&xw, g_xw);
    cudaGetSymbolAddress((void**)&h, g_h);
    cudaGetSymbolAddress((void**)&c, g_c);
    cudaGetSymbolAddress((void**)&ys1, g_ys1);
    cudaGetSymbolAddress((void**)&ys2, g_ys2);
    cudaGetSymbolAddress((void**)&z1, g_z1);
    cudaGetSymbolAddress((void**)&z2, g_z2);

    const int MT = B_ * T_;  // 16384

    // xw = x @ W1 + b1   (rows b*T+t, 16384 x 4096, K=512)
    {
        dim3 grid(G4 / 64, MT / 64);
        sgemm<64, 64, 16><<<grid, 256>>>(x, W1, b1, xw, MT, G4, D_);
    }

    // LSTM layer 1 (persistent, 256 steps internal)
    lstm_layer<<<128, 256>>>(U1, xw, h0, c0, h, c, ys1);

    // xw = ys1 @ W2 + b2  (16384 x 4096, K=1024)
    {
        dim3 grid(G4 / 64, MT / 64);
        sgemm<64, 64, 16><<<grid, 256>>>(ys1, W2, b2, xw, MT, G4, H_);
    }

    // LSTM layer 2 — seeded with layer-1 final states (same h/c buffers)
    lstm_layer<<<128, 256>>>(U2, xw, h, c, h, c, ys2);

    // z1 = ys2 @ fc1_w + fc1_b  (16384 x 512, K=1024); rows b*T+t make this
    // exactly the (B, T*512) flatten the reference uses.
    {
        dim3 grid((H_ / 2) / 64, MT / 64);
        sgemm<64, 64, 16><<<grid, 256>>>(ys2, fc1_w, fc1_b, z1, MT, H_ / 2, H_);
    }

    // fc2: (64, 131072) @ (131072, 36)
    fc2_kernel<<<B_, 256>>>(z1, fc2_w, fc2_b, z2);

    // fc3 + fc4 + relu -> out (64, 6)
    fc34_kernel<<<1, 64>>>(z2, fc3_w, fc3_b, fc4_w, fc4_b, out);
}

// round 4
// speedup vs baseline: 1.0003x; 1.0003x over previous
#include <cuda_runtime.h>
#include <cuda_bf16.h>
#include <math.h>

// Problem constants
constexpr int B_ = 64;
constexpr int T_ = 256;
constexpr int D_ = 512;
constexpr int H_ = 1024;
constexpr int G4 = 4 * H_;         // 4096
constexpr int BH = B_ * H_;        // 65536

// Scratch (device globals — allocation-free per harness rules)
__device__ float g_xw[(size_t)B_ * T_ * G4];        // (B*T, 4H)  268 MB
__device__ float g_h[BH];
__device__ float g_c[BH];
__device__ float g_ys1[(size_t)B_ * T_ * H_];       // (B*T, H)   67 MB
__device__ float g_ys2[(size_t)B_ * T_ * H_];       // (B*T, H)
__device__ float g_z1[(size_t)B_ * T_ * (H_ / 2)];  // (B, T*512)
__device__ float g_z2[B_ * 36];

// -------------------------- software grid barrier --------------------------
__device__ unsigned g_bar_count = 0;
__device__ volatile unsigned g_bar_gen = 0;

__device__ __forceinline__ void grid_barrier(unsigned nblocks)
{
    __syncthreads();
    if (threadIdx.x == 0) {
        __threadfence();                       // make h/c stores visible
        unsigned gen = g_bar_gen;
        if (atomicAdd(&g_bar_count, 1u) == nblocks - 1u) {
            g_bar_count = 0;
            __threadfence();
            g_bar_gen = gen + 1u;
        } else {
            while (g_bar_gen == gen) { }
        }
    }
    __syncthreads();
}

__device__ __forceinline__ float sigmoidf(float x) { return 1.f / (1.f + expf(-x)); }

// ---------------------------------------------------------------------------
// Persistent LSTM layer: 128 CTAs x 256 threads, all resident.
// CTA owns 8 h-columns (j0..j0+7) across all 4 gates (a 64x32 gate tile).
// Per step: SMEM-tiled GEMM tile of h @ U, add xw[t], cell update, 1 barrier.
// xw rows are indexed (b*T + t).  At t==0, h/c come from h0/c0 pointers.
// ---------------------------------------------------------------------------
__global__ void __launch_bounds__(256) lstm_layer(
    const float* __restrict__ U,    // (H, 4H)
    const float* __restrict__ xw,   // (B*T, 4H)
    const float* __restrict__ h0,   // (B, H) initial hidden
    const float* __restrict__ c0,   // (B, H) initial cell
    float* __restrict__ h,          // (B, H) working/final hidden
    float* __restrict__ c,          // (B, H) working/final cell
    float* __restrict__ ys)         // (B*T, H)
{
    const unsigned nblocks = gridDim.x;     // 128
    const int j0 = blockIdx.x * 8;          // 8 j-columns per CTA
    const int tid = threadIdx.x;
    const int ty = tid >> 4;                // 0..15 -> 4 rows each
    const int tx = tid & 15;                // 0..15 -> 2 cols each

    __shared__ float As[16][64];
    __shared__ float Bs[16][32];
    __shared__ float Cs[64][33];            // padded

    for (int t = 0; t < T_; t++) {
        const float* hsrc = (t == 0) ? h0 : h;

        float acc[4][2];
#pragma unroll
        for (int r = 0; r < 4; r++) { acc[r][0] = 0.f; acc[r][1] = 0.f; }

        for (int k0 = 0; k0 < H_; k0 += 16) {
            // A tile: 64 rows x 16 k (one float4 per thread), L2-coherent load
            {
                int r = tid >> 2;                 // 0..63
                int cc = (tid & 3) * 4;           // 0,4,8,12
                float4 av = __ldcg(reinterpret_cast<const float4*>(
                    hsrc + (size_t)r * H_ + k0 + cc));
                As[cc + 0][r] = av.x;
                As[cc + 1][r] = av.y;
                As[cc + 2][r] = av.z;
                As[cc + 3][r] = av.w;
            }
            // B tile: 16 k x 32 cols; col cc -> U column (cc/8)*H + j0 + cc%8
            {
#pragma unroll
                for (int e = 0; e < 2; e++) {
                    int v = tid * 2 + e;
                    int kk = v >> 5;
                    int cc = v & 31;
                    int col = (cc >> 3) * H_ + j0 + (cc & 7);
                    Bs[kk][cc] = U[(size_t)(k0 + kk) * G4 + col];
                }
            }
            __syncthreads();
#pragma unroll
            for (int k = 0; k < 16; k++) {
                const float4 a = *reinterpret_cast<const float4*>(&As[k][ty * 4]);
                const float b0 = Bs[k][tx * 2 + 0];
                const float b1 = Bs[k][tx * 2 + 1];
                acc[0][0] = fmaf(a.x, b0, acc[0][0]);
                acc[1][0] = fmaf(a.y, b0, acc[1][0]);
                acc[2][0] = fmaf(a.z, b0, acc[2][0]);
                acc[3][0] = fmaf(a.w, b0, acc[3][0]);
                acc[0][1] = fmaf(a.x, b1, acc[0][1]);
                acc[1][1] = fmaf(a.y, b1, acc[1][1]);
                acc[2][1] = fmaf(a.z, b1, acc[2][1]);
                acc[3][1] = fmaf(a.w, b1, acc[3][1]);
            }
            __syncthreads();
        }

        // stage tile in SMEM so cell update can use a (b,j)-aligned mapping
#pragma unroll
        for (int r = 0; r < 4; r++) {
            Cs[ty * 4 + r][tx * 2 + 0] = acc[r][0];
            Cs[ty * 4 + r][tx * 2 + 1] = acc[r][1];
        }
        __syncthreads();

        // cell update: 512 cells (64 b x 8 j), 2 per thread
#pragma unroll
        for (int e = 0; e < 2; e++) {
            int cell = tid * 2 + e;
            int b = cell >> 3;
            int jj = cell & 7;
            int col = j0 + jj;
            size_t xrow = ((size_t)b * T_ + t) * G4;
            float iv = Cs[b][0 * 8 + jj] + xw[xrow + 0 * H_ + col];
            float fv = Cs[b][1 * 8 + jj] + xw[xrow + 1 * H_ + col];
            float gv = Cs[b][2 * 8 + jj] + xw[xrow + 2 * H_ + col];
            float ov = Cs[b][3 * 8 + jj] + xw[xrow + 3 * H_ + col];
            int idx = b * H_ + col;
            float cprev = (t == 0) ? c0[idx] : c[idx];
            float cn = sigmoidf(fv) * cprev + sigmoidf(iv) * tanhf(gv);
            float hn = sigmoidf(ov) * tanhf(cn);
            c[idx] = cn;
            h[idx] = hn;
            ys[((size_t)b * T_ + t) * H_ + col] = hn;
        }
        __syncthreads();          // Cs reuse safety for next iteration
        grid_barrier(nblocks);    // h fully updated before next step's reads
    }
}

// ---------------------------------------------------------------------------
// Generic fp32 tiled SGEMM: C = A(MxK) @ B(KxN) + bias(N)
// ---------------------------------------------------------------------------
template <int BM, int BN, int BK>
__global__ void sgemm(const float* __restrict__ A, const float* __restrict__ Bm,
                      const float* __restrict__ bias, float* __restrict__ C,
                      int M, int N, int K)
{
    constexpr int TM = BM / 16;
    constexpr int TN = BN / 16;
    __shared__ float As[BK][BM];
    __shared__ float Bs[BK][BN];

    const int bm = blockIdx.y * BM;
    const int bn = blockIdx.x * BN;
    const int tid = threadIdx.x;
    const int tx = tid & 15;
    const int ty = tid >> 4;

    float acc[TM][TN];
#pragma unroll
    for (int i = 0; i < TM; i++)
#pragma unroll
        for (int j = 0; j < TN; j++) acc[i][j] = 0.f;

    for (int k0 = 0; k0 < K; k0 += BK) {
        for (int v = tid; v < BM * BK / 4; v += 256) {
            int r = v / (BK / 4);
            int cc = (v % (BK / 4)) * 4;
            float4 av = *(const float4*)(A + (size_t)(bm + r) * K + k0 + cc);
            As[cc + 0][r] = av.x;
            As[cc + 1][r] = av.y;
            As[cc + 2][r] = av.z;
            As[cc + 3][r] = av.w;
        }
        for (int v = tid; v < BK * BN / 4; v += 256) {
            int r = v / (BN / 4);
            int cc = (v % (BN / 4)) * 4;
            *(float4*)(&Bs[r][cc]) = *(const float4*)(Bm + (size_t)(k0 + r) * N + bn + cc);
        }
        __syncthreads();
#pragma unroll
        for (int k = 0; k < BK; k++) {
            float ar[TM], br[TN];
#pragma unroll
            for (int i = 0; i < TM; i++) ar[i] = As[k][ty * TM + i];
#pragma unroll
            for (int j = 0; j < TN; j++) br[j] = Bs[k][tx * TN + j];
#pragma unroll
            for (int i = 0; i < TM; i++)
#pragma unroll
                for (int j = 0; j < TN; j++) acc[i][j] = fmaf(ar[i], br[j], acc[i][j]);
        }
        __syncthreads();
    }

#pragma unroll
    for (int i = 0; i < TM; i++) {
        int row = bm + ty * TM + i;
#pragma unroll
        for (int j = 0; j < TN; j++) {
            int col = bn + tx * TN + j;
            float v = acc[i][j];
            if (bias) v += bias[col];
            C[(size_t)row * N + col] = v;
        }
    }
}

// fc2: out(64,36) = A(64,131072) @ W(131072,36) + bias. One block per row m.
__global__ void fc2_kernel(const float* __restrict__ A, const float* __restrict__ W,
                           const float* __restrict__ bias, float* __restrict__ out)
{
    constexpr int K = T_ * (H_ / 2);  // 131072
    int m = blockIdx.x;
    int tid = threadIdx.x;  // 256
    float acc[36];
#pragma unroll
    for (int n = 0; n < 36; n++) acc[n] = 0.f;
    const float* arow = A + (size_t)m * K;
    for (int k = tid; k < K; k += 256) {
        float a = arow[k];
        const float* wr = W + (size_t)k * 36;
#pragma unroll
        for (int n = 0; n < 36; n++) acc[n] = fmaf(a, wr[n], acc[n]);
    }
    __shared__ float red[256];
    for (int n = 0; n < 36; n++) {
        red[tid] = acc[n];
        __syncthreads();
        for (int s = 128; s > 0; s >>= 1) {
            if (tid < s) red[tid] += red[tid + s];
            __syncthreads();
        }
        if (tid == 0) out[m * 36 + n] = red[0] + bias[n];
        __syncthreads();
    }
}

// fc3 (36->6) + fc4 (6->6) + relu; one thread per batch row
__global__ void fc34_kernel(const float* __restrict__ z2,
                            const float* __restrict__ w3, const float* __restrict__ b3,
                            const float* __restrict__ w4, const float* __restrict__ b4,
                            float* __restrict__ out)
{
    int m = threadIdx.x;
    if (m >= B_) return;
    float t3[6];
#pragma unroll
    for (int n = 0; n < 6; n++) {
        float s = b3[n];
        for (int k = 0; k < 36; k++) s = fmaf(z2[m * 36 + k], w3[k * 6 + n], s);
        t3[n] = s;
    }
#pragma unroll
    for (int n = 0; n < 6; n++) {
        float s = b4[n];
#pragma unroll
        for (int k = 0; k < 6; k++) s = fmaf(t3[k], w4[k * 6 + n], s);
        out[m * 6 + n] = fmaxf(s, 0.f);
    }
}

// ---------------------------------------------------------------------------
extern "C" void kernel_launch(void* const* d_in, const int* in_sizes, int n_in,
                              void* d_out, int out_size)
{
    const float* x     = (const float*)d_in[0];   // (B,T,D) == (B*T, D) rows b*T+t
    const float* h0    = (const float*)d_in[1];
    const float* c0    = (const float*)d_in[2];
    const float* W1    = (const float*)d_in[3];
    const float* U1    = (const float*)d_in[4];
    const float* b1    = (const float*)d_in[5];
    const float* W2    = (const float*)d_in[6];
    const float* U2    = (const float*)d_in[7];
    const float* b2    = (const float*)d_in[8];
    const float* fc1_w = (const float*)d_in[9];
    const float* fc1_b = (const float*)d_in[10];
    const float* fc2_w = (const float*)d_in[11];
    const float* fc2_b = (const float*)d_in[12];
    const float* fc3_w = (const float*)d_in[13];
    const float* fc3_b = (const float*)d_in[14];
    const float* fc4_w = (const float*)d_in[15];
    const float* fc4_b = (const float*)d_in[16];
    float* out = (float*)d_out;

    float *xw, *h, *c, *ys1, *ys2, *z1, *z2;
    cudaGetSymbolAddress((void**)&xw, g_xw);
    cudaGetSymbolAddress((void**)&h, g_h);
    cudaGetSymbolAddress((void**)&c, g_c);
    cudaGetSymbolAddress((void**)&ys1, g_ys1);
    cudaGetSymbolAddress((void**)&ys2, g_ys2);
    cudaGetSymbolAddress((void**)&z1, g_z1);
    cudaGetSymbolAddress((void**)&z2, g_z2);

    const int MT = B_ * T_;  // 16384

    // xw = x @ W1 + b1   (rows b*T+t, 16384 x 4096, K=512)
    {
        dim3 grid(G4 / 64, MT / 64);
        sgemm<64, 64, 16><<<grid, 256>>>(x, W1, b1, xw, MT, G4, D_);
    }

    // LSTM layer 1 (persistent, 256 steps internal)
    lstm_layer<<<128, 256>>>(U1, xw, h0, c0, h, c, ys1);

    // xw = ys1 @ W2 + b2  (16384 x 4096, K=1024)
    {
        dim3 grid(G4 / 64, MT / 64);
        sgemm<64, 64, 16><<<grid, 256>>>(ys1, W2, b2, xw, MT, G4, H_);
    }

    // LSTM layer 2 — seeded with layer-1 final states (same h/c buffers)
    lstm_layer<<<128, 256>>>(U2, xw, h, c, h, c, ys2);

    // z1 = ys2 @ fc1_w + fc1_b  (16384 x 512, K=1024); rows b*T+t make this
    // exactly the (B, T*512) flatten the reference uses.
    {
        dim3 grid((H_ / 2) / 64, MT / 64);
        sgemm<64, 64, 16><<<grid, 256>>>(ys2, fc1_w, fc1_b, z1, MT, H_ / 2, H_);
    }

    // fc2: (64, 131072) @ (131072, 36)
    fc2_kernel<<<B_, 256>>>(z1, fc2_w, fc2_b, z2);

    // fc3 + fc4 + relu -> out (64, 6)
    fc34_kernel<<<1, 64>>>(z2, fc3_w, fc3_b, fc4_w, fc4_b, out);
}

// round 5
// speedup vs baseline: 5.1313x; 5.1295x over previous
#include <cuda_runtime.h>
#include <cuda_fp16.h>
#include <math.h>
#include <stdint.h>

// Problem constants
constexpr int B_ = 64;
constexpr int T_ = 256;
constexpr int D_ = 512;
constexpr int H_ = 1024;
constexpr int G4 = 4 * H_;         // 4096
constexpr int BH = B_ * H_;        // 65536

// ------------------------- device scratch (no allocs) ----------------------
__device__ float  g_xw[(size_t)B_ * T_ * G4];        // (B*T, 4H) fp32, 268 MB
__device__ float  g_c[BH];                           // cell state fp32
__device__ __half g_h16[BH];                         // hidden state fp16
__device__ __half g_x16[(size_t)B_ * T_ * D_];       // x in fp16
__device__ __half g_W1_16[(size_t)D_ * G4];
__device__ __half g_U1_16[(size_t)H_ * G4];
__device__ __half g_W2_16[(size_t)H_ * G4];
__device__ __half g_U2_16[(size_t)H_ * G4];
__device__ __half g_fc1w16[(size_t)H_ * (H_ / 2)];
__device__ __half g_ys1_16[(size_t)B_ * T_ * H_];    // fp16 LSTM outputs
__device__ __half g_ys2_16[(size_t)B_ * T_ * H_];
__device__ float  g_z1[(size_t)B_ * T_ * (H_ / 2)];  // (B, T*512) fp32
__device__ float  g_z2[B_ * 36];

// ------------------------------ PTX helpers --------------------------------
__device__ __forceinline__ uint32_t smem_u32(const void* p) {
    uint32_t a;
    asm("{ .reg .u64 t; cvta.to.shared.u64 t, %1; cvt.u32.u64 %0, t; }"
        : "=r"(a) : "l"(p));
    return a;
}
__device__ __forceinline__ void cp_async16(uint32_t dst, const void* src) {
    asm volatile("cp.async.cg.shared.global [%0], [%1], 16;" :: "r"(dst), "l"(src));
}
__device__ __forceinline__ void cp_commit() {
    asm volatile("cp.async.commit_group;");
}
__device__ __forceinline__ void cp_wait0() {
    asm volatile("cp.async.wait_group 0;");
}
__device__ __forceinline__ void ldmatrix_x4(uint32_t* r, uint32_t addr) {
    asm volatile("ldmatrix.sync.aligned.m8n8.x4.shared.b16 {%0,%1,%2,%3}, [%4];"
                 : "=r"(r[0]), "=r"(r[1]), "=r"(r[2]), "=r"(r[3]) : "r"(addr));
}
__device__ __forceinline__ void ldmatrix_x2t(uint32_t* r, uint32_t addr) {
    asm volatile("ldmatrix.sync.aligned.m8n8.x2.trans.shared.b16 {%0,%1}, [%2];"
                 : "=r"(r[0]), "=r"(r[1]) : "r"(addr));
}
__device__ __forceinline__ void mma16816(float* d, const uint32_t* a, const uint32_t* b) {
    asm volatile(
        "mma.sync.aligned.m16n8k16.row.col.f32.f16.f16.f32 "
        "{%0,%1,%2,%3},{%4,%5,%6,%7},{%8,%9},{%0,%1,%2,%3};"
        : "+f"(d[0]), "+f"(d[1]), "+f"(d[2]), "+f"(d[3])
        : "r"(a[0]), "r"(a[1]), "r"(a[2]), "r"(a[3]), "r"(b[0]), "r"(b[1]));
}

// -------------------------- software grid barrier --------------------------
__device__ unsigned g_bar_count = 0;
__device__ volatile unsigned g_bar_gen = 0;

__device__ __forceinline__ void grid_barrier(unsigned nblocks)
{
    __syncthreads();
    if (threadIdx.x == 0) {
        __threadfence();
        unsigned gen = g_bar_gen;
        if (atomicAdd(&g_bar_count, 1u) == nblocks - 1u) {
            g_bar_count = 0;
            __threadfence();
            g_bar_gen = gen + 1u;
        } else {
            while (g_bar_gen == gen) { }
        }
    }
    __syncthreads();
}

__device__ __forceinline__ float sigmoidf_(float x) { return 1.f / (1.f + expf(-x)); }

// ---------------------------------------------------------------------------
// fp32 -> fp16 conversion (n % 4 == 0)
// ---------------------------------------------------------------------------
__global__ void f32_to_f16(const float* __restrict__ in, __half* __restrict__ out, int n)
{
    int i4 = (blockIdx.x * 256 + threadIdx.x) * 4;
    if (i4 < n) {
        float4 v = *reinterpret_cast<const float4*>(in + i4);
        *reinterpret_cast<__half2*>(out + i4)     = __floats2half2_rn(v.x, v.y);
        *reinterpret_cast<__half2*>(out + i4 + 2) = __floats2half2_rn(v.z, v.w);
    }
}

__global__ void init_state16(const float* __restrict__ h0, const float* __restrict__ c0,
                             __half* __restrict__ h16, float* __restrict__ c)
{
    int i = blockIdx.x * 256 + threadIdx.x;
    if (i < BH) { h16[i] = __float2half_rn(h0[i]); c[i] = c0[i]; }
}

// ---------------------------------------------------------------------------
// HGEMM: C_fp32(M,N) = A_fp16(M,K) @ B_fp16(K,N) + bias(N)
// 128x128x32 tile, 256 threads (2x4 warps, each 64x32), double-buffered cp.async
// Requires M%128==0, N%128==0, K%32==0.
// ---------------------------------------------------------------------------
__global__ void __launch_bounds__(256) hgemm(
    const __half* __restrict__ A, const __half* __restrict__ Bm,
    const float* __restrict__ bias, float* __restrict__ C,
    int M, int N, int K)
{
    __shared__ __half As[2][128 * 40];   // rows padded to 40 halfs
    __shared__ __half Bs[2][32 * 136];   // rows padded to 136 halfs

    const int tid = threadIdx.x;
    const int w = tid >> 5, lane = tid & 31;
    const int bm = blockIdx.y * 128, bn = blockIdx.x * 128;
    const int wm = (w >> 2) * 64, wn = (w & 3) * 32;
    const uint32_t AsU = smem_u32(As), BsU = smem_u32(Bs);

    float acc[4][4][4];
#pragma unroll
    for (int i = 0; i < 4; i++)
#pragma unroll
        for (int j = 0; j < 4; j++)
#pragma unroll
            for (int e = 0; e < 4; e++) acc[i][j][e] = 0.f;

    const int nk = K / 32;

#define LOAD_TILE(kt, buf)                                                        \
    {                                                                             \
        int k0 = (kt) * 32;                                                       \
        _Pragma("unroll")                                                         \
        for (int e = 0; e < 2; e++) {                                             \
            int idx = tid + e * 256;                                              \
            int r = idx >> 2, ch = idx & 3;                                       \
            cp_async16(AsU + ((buf) * 5120 + r * 40 + ch * 8) * 2,                \
                       A + (size_t)(bm + r) * K + k0 + ch * 8);                   \
        }                                                                         \
        _Pragma("unroll")                                                         \
        for (int e = 0; e < 2; e++) {                                             \
            int idx = tid + e * 256;                                              \
            int r = idx >> 4, ch = idx & 15;                                      \
            cp_async16(BsU + ((buf) * 4352 + r * 136 + ch * 8) * 2,               \
                       Bm + (size_t)(k0 + r) * N + bn + ch * 8);                  \
        }                                                                         \
        cp_commit();                                                              \
    }

    LOAD_TILE(0, 0)
    cp_wait0();
    __syncthreads();

    for (int kt = 0; kt < nk; kt++) {
        int buf = kt & 1;
        if (kt + 1 < nk) LOAD_TILE(kt + 1, buf ^ 1)

#pragma unroll
        for (int ks = 0; ks < 2; ks++) {
            uint32_t bfr[4][2];
#pragma unroll
            for (int nf = 0; nf < 4; nf++)
                ldmatrix_x2t(bfr[nf],
                    BsU + (buf * 4352 + (ks * 16 + (lane & 15)) * 136 + wn + nf * 8) * 2);
#pragma unroll
            for (int mf = 0; mf < 4; mf++) {
                uint32_t afr[4];
                ldmatrix_x4(afr,
                    AsU + (buf * 5120 + (wm + mf * 16 + (lane & 15)) * 40
                           + ks * 16 + ((lane >> 4) * 8)) * 2);
#pragma unroll
                for (int nf = 0; nf < 4; nf++) mma16816(acc[mf][nf], afr, bfr[nf]);
            }
        }
        if (kt + 1 < nk) cp_wait0();
        __syncthreads();
    }
#undef LOAD_TILE

    const int g = lane >> 2, t4 = lane & 3;
#pragma unroll
    for (int mf = 0; mf < 4; mf++)
#pragma unroll
        for (int nf = 0; nf < 4; nf++) {
            int row0 = bm + wm + mf * 16 + g;
            int col = bn + wn + nf * 8 + t4 * 2;
            float b0 = bias ? bias[col] : 0.f;
            float b1 = bias ? bias[col + 1] : 0.f;
            C[(size_t)row0 * N + col]           = acc[mf][nf][0] + b0;
            C[(size_t)row0 * N + col + 1]       = acc[mf][nf][1] + b1;
            C[(size_t)(row0 + 8) * N + col]     = acc[mf][nf][2] + b0;
            C[(size_t)(row0 + 8) * N + col + 1] = acc[mf][nf][3] + b1;
        }
}

// ---------------------------------------------------------------------------
// Persistent tensor-core LSTM layer. 128 CTAs x 256 threads (8 warps).
// CTA owns 8 h-columns j0..j0+7 -> 32 gate columns {g*1024 + j0 + jj}.
// U slice (1024 x 32, padded rows of 40) preloaded in SMEM once.
// Per step: stage h16 (64x1024) -> SMEM via cp.async.cg, split-K mma over
// 8 warps, SMEM reduce, fused cell update, grid barrier.
// dyn smem = 81920 (U) + 132096 (A/red alias) = 214016 B
// ---------------------------------------------------------------------------
constexpr int LSTM_SMEM = 81920 + 64 * 1032 * 2;  // 214016

__global__ void __launch_bounds__(256) lstm_layer_tc(
    const __half* __restrict__ U16,   // (1024, 4096) fp16
    const float* __restrict__ xw,     // (B*T, 4096) fp32, rows b*T+t
    float* __restrict__ c,            // (B,1024) fp32 state (pre-seeded)
    __half* __restrict__ h16,         // (B,1024) fp16 state (pre-seeded)
    __half* __restrict__ ys16)        // (B*T, 1024) fp16 out
{
    extern __shared__ char sm[];
    __half* U_s = (__half*)sm;                    // [1024][40]
    __half* A_s = (__half*)(sm + 81920);          // [64][1032]
    float*  red = (float*)(sm + 81920);           // [8][64][33] alias (67584B)
    const uint32_t U_u = smem_u32(U_s);
    const uint32_t A_u = smem_u32(A_s);

    const int tid = threadIdx.x;
    const int w = tid >> 5, lane = tid & 31;
    const int j0 = blockIdx.x * 8;
    const int kbase = w * 128;

    // preload this CTA's U slice: 1024 rows x 4 gate-chunks of 8 halfs
#pragma unroll
    for (int i = 0; i < 16; i++) {
        int idx = tid + i * 256;
        int k = idx >> 2, g = idx & 3;
        *reinterpret_cast<uint4*>(U_s + k * 40 + g * 8) =
            *reinterpret_cast<const uint4*>(U16 + (size_t)k * G4 + g * H_ + j0);
    }
    __syncthreads();

    const int gg_ = lane >> 2, t4 = lane & 3;

    for (int t = 0; t < T_; t++) {
        // stage h16 (64 x 1024) into A_s — cp.async.cg bypasses stale L1
#pragma unroll
        for (int i = 0; i < 32; i++) {
            int idx = tid + i * 256;
            int r = idx >> 7, ch = idx & 127;
            cp_async16(A_u + (r * 1032 + ch * 8) * 2, h16 + r * 1024 + ch * 8);
        }
        cp_commit();
        cp_wait0();
        __syncthreads();

        float acc[4][4][4];
#pragma unroll
        for (int i = 0; i < 4; i++)
#pragma unroll
            for (int j = 0; j < 4; j++)
#pragma unroll
                for (int e = 0; e < 4; e++) acc[i][j][e] = 0.f;

#pragma unroll
        for (int ks = 0; ks < 8; ks++) {
            int kk = kbase + ks * 16;
            uint32_t bfr[4][2];
#pragma unroll
            for (int nf = 0; nf < 4; nf++)
                ldmatrix_x2t(bfr[nf], U_u + ((kk + (lane & 15)) * 40 + nf * 8) * 2);
#pragma unroll
            for (int mf = 0; mf < 4; mf++) {
                uint32_t afr[4];
                ldmatrix_x4(afr, A_u + ((mf * 16 + (lane & 15)) * 1032
                                        + kk + (lane >> 4) * 8) * 2);
#pragma unroll
                for (int nf = 0; nf < 4; nf++) mma16816(acc[mf][nf], afr, bfr[nf]);
            }
        }
        __syncthreads();  // all warps done reading A_s before red alias writes

        // stash per-warp partials: red[w][m][col], rows padded to 33
#pragma unroll
        for (int mf = 0; mf < 4; mf++)
#pragma unroll
            for (int nf = 0; nf < 4; nf++) {
                int m0 = mf * 16 + gg_;
                int col = nf * 8 + t4 * 2;
                red[(w * 64 + m0) * 33 + col]         = acc[mf][nf][0];
                red[(w * 64 + m0) * 33 + col + 1]     = acc[mf][nf][1];
                red[(w * 64 + m0 + 8) * 33 + col]     = acc[mf][nf][2];
                red[(w * 64 + m0 + 8) * 33 + col + 1] = acc[mf][nf][3];
            }
        __syncthreads();

        // cell update: 512 cells (64 b x 8 jj), 2 per thread
#pragma unroll
        for (int e = 0; e < 2; e++) {
            int cell = tid * 2 + e;
            int b = cell >> 3, jj = cell & 7;
            size_t xb = ((size_t)b * T_ + t) * (size_t)G4 + j0 + jj;
            float gt[4];
#pragma unroll
            for (int gg = 0; gg < 4; gg++) {
                float s = xw[xb + (size_t)gg * H_];
#pragma unroll
                for (int ww = 0; ww < 8; ww++)
                    s += red[(ww * 64 + b) * 33 + gg * 8 + jj];
                gt[gg] = s;
            }
            int idx = b * H_ + j0 + jj;
            float cn = sigmoidf_(gt[1]) * c[idx] + sigmoidf_(gt[0]) * tanhf(gt[2]);
            float hn = sigmoidf_(gt[3]) * tanhf(cn);
            c[idx] = cn;
            __half hh = __float2half_rn(hn);
            h16[idx] = hh;
            ys16[((size_t)b * T_ + t) * (size_t)H_ + j0 + jj] = hh;
        }
        grid_barrier(gridDim.x);
    }
}

// ---------------------------------------------------------------------------
// fc2: out(64,36) = A(64,131072) @ W(131072,36) + bias. One block per row m.
// ---------------------------------------------------------------------------
__global__ void fc2_kernel(const float* __restrict__ A, const float* __restrict__ W,
                           const float* __restrict__ bias, float* __restrict__ out)
{
    constexpr int K = T_ * (H_ / 2);  // 131072
    int m = blockIdx.x;
    int tid = threadIdx.x;  // 256
    float acc[36];
#pragma unroll
    for (int n = 0; n < 36; n++) acc[n] = 0.f;
    const float* arow = A + (size_t)m * K;
    for (int k = tid; k < K; k += 256) {
        float a = arow[k];
        const float* wr = W + (size_t)k * 36;
#pragma unroll
        for (int n = 0; n < 36; n++) acc[n] = fmaf(a, wr[n], acc[n]);
    }
    __shared__ float red[256];
    for (int n = 0; n < 36; n++) {
        red[tid] = acc[n];
        __syncthreads();
        for (int s = 128; s > 0; s >>= 1) {
            if (tid < s) red[tid] += red[tid + s];
            __syncthreads();
        }
        if (tid == 0) out[m * 36 + n] = red[0] + bias[n];
        __syncthreads();
    }
}

// fc3 (36->6) + fc4 (6->6) + relu
__global__ void fc34_kernel(const float* __restrict__ z2,
                            const float* __restrict__ w3, const float* __restrict__ b3,
                            const float* __restrict__ w4, const float* __restrict__ b4,
                            float* __restrict__ out)
{
    int m = threadIdx.x;
    if (m >= B_) return;
    float t3[6];
#pragma unroll
    for (int n = 0; n < 6; n++) {
        float s = b3[n];
        for (int k = 0; k < 36; k++) s = fmaf(z2[m * 36 + k], w3[k * 6 + n], s);
        t3[n] = s;
    }
#pragma unroll
    for (int n = 0; n < 6; n++) {
        float s = b4[n];
#pragma unroll
        for (int k = 0; k < 6; k++) s = fmaf(t3[k], w4[k * 6 + n], s);
        out[m * 6 + n] = fmaxf(s, 0.f);
    }
}

// ---------------------------------------------------------------------------
extern "C" void kernel_launch(void* const* d_in, const int* in_sizes, int n_in,
                              void* d_out, int out_size)
{
    const float* x     = (const float*)d_in[0];   // (B,T,D): rows b*T+t
    const float* h0    = (const float*)d_in[1];
    const float* c0    = (const float*)d_in[2];
    const float* W1    = (const float*)d_in[3];
    const float* U1    = (const float*)d_in[4];
    const float* b1    = (const float*)d_in[5];
    const float* W2    = (const float*)d_in[6];
    const float* U2    = (const float*)d_in[7];
    const float* b2    = (const float*)d_in[8];
    const float* fc1_w = (const float*)d_in[9];
    const float* fc1_b = (const float*)d_in[10];
    const float* fc2_w = (const float*)d_in[11];
    const float* fc2_b = (const float*)d_in[12];
    const float* fc3_w = (const float*)d_in[13];
    const float* fc3_b = (const float*)d_in[14];
    const float* fc4_w = (const float*)d_in[15];
    const float* fc4_b = (const float*)d_in[16];
    float* out = (float*)d_out;

    float *xw, *c, *z1, *z2;
    __half *h16, *x16, *W1_16, *U1_16, *W2_16, *U2_16, *fc1w16, *ys1_16, *ys2_16;
    cudaGetSymbolAddress((void**)&xw, g_xw);
    cudaGetSymbolAddress((void**)&c, g_c);
    cudaGetSymbolAddress((void**)&h16, g_h16);
    cudaGetSymbolAddress((void**)&x16, g_x16);
    cudaGetSymbolAddress((void**)&W1_16, g_W1_16);
    cudaGetSymbolAddress((void**)&U1_16, g_U1_16);
    cudaGetSymbolAddress((void**)&W2_16, g_W2_16);
    cudaGetSymbolAddress((void**)&U2_16, g_U2_16);
    cudaGetSymbolAddress((void**)&fc1w16, g_fc1w16);
    cudaGetSymbolAddress((void**)&ys1_16, g_ys1_16);
    cudaGetSymbolAddress((void**)&ys2_16, g_ys2_16);
    cudaGetSymbolAddress((void**)&z1, g_z1);
    cudaGetSymbolAddress((void**)&z2, g_z2);

    static bool attr_done = false;
    if (!attr_done) {
        cudaFuncSetAttribute(lstm_layer_tc,
                             cudaFuncAttributeMaxDynamicSharedMemorySize, LSTM_SMEM);
        attr_done = true;
    }

    const int MT = B_ * T_;  // 16384

    // fp32 -> fp16 conversions
    auto conv = [](const float* src, __half* dst, int n) {
        f32_to_f16<<<(n / 4 + 255) / 256, 256>>>(src, dst, n);
    };
    conv(x, x16, MT * D_);
    conv(W1, W1_16, D_ * G4);
    conv(U1, U1_16, H_ * G4);
    conv(W2, W2_16, H_ * G4);
    conv(U2, U2_16, H_ * G4);
    conv(fc1_w, fc1w16, H_ * (H_ / 2));
    init_state16<<<BH / 256, 256>>>(h0, c0, h16, c);

    // xw = x @ W1 + b1   (16384 x 4096, K=512)
    hgemm<<<dim3(G4 / 128, MT / 128), 256>>>(x16, W1_16, b1, xw, MT, G4, D_);

    // LSTM layer 1 (persistent, tensor cores)
    lstm_layer_tc<<<128, 256, LSTM_SMEM>>>(U1_16, xw, c, h16, ys1_16);

    // xw = ys1 @ W2 + b2  (16384 x 4096, K=1024)
    hgemm<<<dim3(G4 / 128, MT / 128), 256>>>(ys1_16, W2_16, b2, xw, MT, G4, H_);

    // LSTM layer 2 (h16/c carry over from layer 1 — matches reference seeding)
    lstm_layer_tc<<<128, 256, LSTM_SMEM>>>(U2_16, xw, c, h16, ys2_16);

    // z1 = ys2 @ fc1_w + fc1_b  (16384 x 512, K=1024)
    hgemm<<<dim3((H_ / 2) / 128, MT / 128), 256>>>(ys2_16, fc1w16, fc1_b, z1,
                                                   MT, H_ / 2, H_);

    // fc2: (64, 131072) @ (131072, 36)
    fc2_kernel<<<B_, 256>>>(z1, fc2_w, fc2_b, z2);

    // fc3 + fc4 + relu -> out (64, 6)
    fc34_kernel<<<1, 64>>>(z2, fc3_w, fc3_b, fc4_w, fc4_b, out);
}

// round 6
// speedup vs baseline: 6.9442x; 1.3533x over previous
#include <cuda_runtime.h>
#include <cuda_fp16.h>
#include <math.h>
#include <stdint.h>

// Problem constants
constexpr int B_ = 64;
constexpr int T_ = 256;
constexpr int D_ = 512;
constexpr int H_ = 1024;
constexpr int G4 = 4 * H_;         // 4096
constexpr int BH = B_ * H_;        // 65536

// ------------------------- device scratch (no allocs) ----------------------
__device__ float  g_xw[(size_t)B_ * T_ * G4];        // (B*T, 4H) fp32
__device__ float  g_c[BH];                           // cell state fp32
__device__ __half g_h16[BH];                         // hidden state fp16
__device__ __half g_x16[(size_t)B_ * T_ * D_];
__device__ __half g_W1_16[(size_t)D_ * G4];
__device__ __half g_U1_16[(size_t)H_ * G4];
__device__ __half g_W2_16[(size_t)H_ * G4];
__device__ __half g_U2_16[(size_t)H_ * G4];
__device__ __half g_fc1w16[(size_t)H_ * (H_ / 2)];
__device__ __half g_ys1_16[(size_t)B_ * T_ * H_];
__device__ __half g_ys2_16[(size_t)B_ * T_ * H_];
__device__ float  g_z1[(size_t)B_ * T_ * (H_ / 2)];
__device__ float  g_z2[B_ * 36];

// ------------------------------ PTX helpers --------------------------------
__device__ __forceinline__ uint32_t smem_u32(const void* p) {
    uint32_t a;
    asm("{ .reg .u64 t; cvta.to.shared.u64 t, %1; cvt.u32.u64 %0, t; }"
        : "=r"(a) : "l"(p));
    return a;
}
__device__ __forceinline__ void cp_async16(uint32_t dst, const void* src) {
    asm volatile("cp.async.cg.shared.global [%0], [%1], 16;" :: "r"(dst), "l"(src));
}
__device__ __forceinline__ void cp_commit() {
    asm volatile("cp.async.commit_group;");
}
template <int N> __device__ __forceinline__ void cp_wait_n() {
    asm volatile("cp.async.wait_group %0;" :: "n"(N));
}
__device__ __forceinline__ void ldmatrix_x4(uint32_t* r, uint32_t addr) {
    asm volatile("ldmatrix.sync.aligned.m8n8.x4.shared.b16 {%0,%1,%2,%3}, [%4];"
                 : "=r"(r[0]), "=r"(r[1]), "=r"(r[2]), "=r"(r[3]) : "r"(addr));
}
__device__ __forceinline__ void ldmatrix_x2t(uint32_t* r, uint32_t addr) {
    asm volatile("ldmatrix.sync.aligned.m8n8.x2.trans.shared.b16 {%0,%1}, [%2];"
                 : "=r"(r[0]), "=r"(r[1]) : "r"(addr));
}
__device__ __forceinline__ void mma16816(float* d, const uint32_t* a, const uint32_t* b) {
    asm volatile(
        "mma.sync.aligned.m16n8k16.row.col.f32.f16.f16.f32 "
        "{%0,%1,%2,%3},{%4,%5,%6,%7},{%8,%9},{%0,%1,%2,%3};"
        : "+f"(d[0]), "+f"(d[1]), "+f"(d[2]), "+f"(d[3])
        : "r"(a[0]), "r"(a[1]), "r"(a[2]), "r"(a[3]), "r"(b[0]), "r"(b[1]));
}

// -------------------------- software grid barrier --------------------------
__device__ unsigned g_bar_count = 0;
__device__ volatile unsigned g_bar_gen = 0;

__device__ __forceinline__ void grid_barrier(unsigned nblocks)
{
    __syncthreads();
    if (threadIdx.x == 0) {
        __threadfence();
        unsigned gen = g_bar_gen;
        if (atomicAdd(&g_bar_count, 1u) == nblocks - 1u) {
            g_bar_count = 0;
            __threadfence();
            g_bar_gen = gen + 1u;
        } else {
            while (g_bar_gen == gen) { }
        }
    }
    __syncthreads();
}

__device__ __forceinline__ float sigmoidf_(float x) { return 1.f / (1.f + expf(-x)); }

// ---------------------------------------------------------------------------
__global__ void f32_to_f16(const float* __restrict__ in, __half* __restrict__ out, int n)
{
    int i4 = (blockIdx.x * 256 + threadIdx.x) * 4;
    if (i4 < n) {
        float4 v = *reinterpret_cast<const float4*>(in + i4);
        *reinterpret_cast<__half2*>(out + i4)     = __floats2half2_rn(v.x, v.y);
        *reinterpret_cast<__half2*>(out + i4 + 2) = __floats2half2_rn(v.z, v.w);
    }
}

__global__ void init_h16(const float* __restrict__ h0, __half* __restrict__ h16)
{
    int i = blockIdx.x * 256 + threadIdx.x;
    if (i < BH) h16[i] = __float2half_rn(h0[i]);
}

// ---------------------------------------------------------------------------
// HGEMM: C_fp32(M,N) = A_fp16(M,K) @ B_fp16(K,N) + bias(N)
// 128x128x32 tile, 256 threads, double-buffered cp.async.
// ---------------------------------------------------------------------------
__global__ void __launch_bounds__(256) hgemm(
    const __half* __restrict__ A, const __half* __restrict__ Bm,
    const float* __restrict__ bias, float* __restrict__ C,
    int M, int N, int K)
{
    __shared__ __half As[2][128 * 40];
    __shared__ __half Bs[2][32 * 136];

    const int tid = threadIdx.x;
    const int w = tid >> 5, lane = tid & 31;
    const int bm = blockIdx.y * 128, bn = blockIdx.x * 128;
    const int wm = (w >> 2) * 64, wn = (w & 3) * 32;
    const uint32_t AsU = smem_u32(As), BsU = smem_u32(Bs);

    float acc[4][4][4];
#pragma unroll
    for (int i = 0; i < 4; i++)
#pragma unroll
        for (int j = 0; j < 4; j++)
#pragma unroll
            for (int e = 0; e < 4; e++) acc[i][j][e] = 0.f;

    const int nk = K / 32;

#define LOAD_TILE(kt, buf)                                                        \
    {                                                                             \
        int k0 = (kt) * 32;                                                       \
        _Pragma("unroll")                                                         \
        for (int e = 0; e < 2; e++) {                                             \
            int idx = tid + e * 256;                                              \
            int r = idx >> 2, ch = idx & 3;                                       \
            cp_async16(AsU + ((buf) * 5120 + r * 40 + ch * 8) * 2,                \
                       A + (size_t)(bm + r) * K + k0 + ch * 8);                   \
        }                                                                         \
        _Pragma("unroll")                                                         \
        for (int e = 0; e < 2; e++) {                                             \
            int idx = tid + e * 256;                                              \
            int r = idx >> 4, ch = idx & 15;                                      \
            cp_async16(BsU + ((buf) * 4352 + r * 136 + ch * 8) * 2,               \
                       Bm + (size_t)(k0 + r) * N + bn + ch * 8);                  \
        }                                                                         \
        cp_commit();                                                              \
    }

    LOAD_TILE(0, 0)
    cp_wait_n<0>();
    __syncthreads();

    for (int kt = 0; kt < nk; kt++) {
        int buf = kt & 1;
        if (kt + 1 < nk) LOAD_TILE(kt + 1, buf ^ 1)

#pragma unroll
        for (int ks = 0; ks < 2; ks++) {
            uint32_t bfr[4][2];
#pragma unroll
            for (int nf = 0; nf < 4; nf++)
                ldmatrix_x2t(bfr[nf],
                    BsU + (buf * 4352 + (ks * 16 + (lane & 15)) * 136 + wn + nf * 8) * 2);
#pragma unroll
            for (int mf = 0; mf < 4; mf++) {
                uint32_t afr[4];
                ldmatrix_x4(afr,
                    AsU + (buf * 5120 + (wm + mf * 16 + (lane & 15)) * 40
                           + ks * 16 + ((lane >> 4) * 8)) * 2);
#pragma unroll
                for (int nf = 0; nf < 4; nf++) mma16816(acc[mf][nf], afr, bfr[nf]);
            }
        }
        if (kt + 1 < nk) cp_wait_n<0>();
        __syncthreads();
    }
#undef LOAD_TILE

    const int g = lane >> 2, t4 = lane & 3;
#pragma unroll
    for (int mf = 0; mf < 4; mf++)
#pragma unroll
        for (int nf = 0; nf < 4; nf++) {
            int row0 = bm + wm + mf * 16 + g;
            int col = bn + wn + nf * 8 + t4 * 2;
            float b0 = bias ? bias[col] : 0.f;
            float b1 = bias ? bias[col + 1] : 0.f;
            C[(size_t)row0 * N + col]           = acc[mf][nf][0] + b0;
            C[(size_t)row0 * N + col + 1]       = acc[mf][nf][1] + b1;
            C[(size_t)(row0 + 8) * N + col]     = acc[mf][nf][2] + b0;
            C[(size_t)(row0 + 8) * N + col + 1] = acc[mf][nf][3] + b1;
        }
}

// ---------------------------------------------------------------------------
// Persistent tensor-core LSTM v2. 128 CTAs = 64 j-groups x 2 batch halves.
// CTA: M=32 batch rows, 16 j-cols (64 gate cols), K=1024 — no k-split.
// Warp w owns j pair (j0+2w, j0+2w+1); its gate cols in SMEM order
// [i·ja,i·jb,f·ja,f·jb,g·ja,g·jb,o·ja,o·jb] so col = 2*gate + jj.
// U slice resident in SMEM (147KB); h staged per step in 4 cp.async chunks
// overlapped with mma; c carried in registers across all steps.
// ---------------------------------------------------------------------------
constexpr int U_BYTES   = 1024 * 72 * 2;   // 147456
constexpr int A_BYTES   = 32 * 1032 * 2;   // 66048
constexpr int LSTM_SMEM = U_BYTES + A_BYTES;  // 213504

__global__ void __launch_bounds__(256) lstm_layer_tc2(
    const __half* __restrict__ U16,   // (1024, 4096) fp16
    const float* __restrict__ xw,     // (B*T, 4096) fp32, rows b*T+t
    const float* __restrict__ cseed,  // (B,1024) fp32 initial cell
    float* __restrict__ cout,         // (B,1024) fp32 final cell
    __half* __restrict__ h16,         // (B,1024) fp16 state (pre-seeded)
    __half* __restrict__ ys16)        // (B*T, 1024) fp16 out
{
    extern __shared__ char sm[];
    __half* U_s = (__half*)sm;                 // [1024][72]
    __half* A_s = (__half*)(sm + U_BYTES);     // [32][1032]
    float*  red = (float*)(sm + U_BYTES);      // alias: per-warp [32][10] fp32
    const uint32_t U_u = smem_u32(U_s);
    const uint32_t A_u = smem_u32(A_s);

    const int tid = threadIdx.x;
    const int w = tid >> 5, lane = tid & 31;
    const int jg = blockIdx.x >> 1;            // 0..63
    const int bh = blockIdx.x & 1;             // batch half
    const int j0 = jg * 16;

    // ---- preload U slice: U_s[k][w*8 + 2*gate + jj] = U16[k][gate*H + j0 + 2w + jj]
    for (int i = 0; i < 128; i++) {
        int idx = tid + i * 256;               // 32768 half2 loads
        int k = idx >> 5;
        int gate = (idx >> 3) & 3;
        int ww = idx & 7;
        *reinterpret_cast<__half2*>(U_s + k * 72 + ww * 8 + 2 * gate) =
            *reinterpret_cast<const __half2*>(U16 + (size_t)k * G4 + gate * H_ + j0 + 2 * ww);
    }
    __syncthreads();

    // ---- per-lane persistent cell state: b = bh*32 + lane, j = j0+2w, j0+2w+1
    const int bloc = bh * 32 + lane;
    float2 creg = *reinterpret_cast<const float2*>(cseed + (size_t)bloc * H_ + j0 + 2 * w);

    const __half* hg = h16 + (size_t)bh * 32 * H_;
    float* redw = red + w * 320;               // [32][10]

    for (int t = 0; t < T_; t++) {
        // issue all 4 h-staging chunks (256 cols each)
#pragma unroll
        for (int cch = 0; cch < 4; cch++) {
#pragma unroll
            for (int e = 0; e < 4; e++) {
                int idx = tid + e * 256;
                int r = idx >> 5, ch = idx & 31;
                cp_async16(A_u + (r * 1032 + cch * 256 + ch * 8) * 2,
                           hg + (size_t)r * H_ + cch * 256 + ch * 8);
            }
            cp_commit();
        }

        // prefetch xw for this lane's two cells (hidden under mma)
        float2 xg[4];
        {
            size_t xbase = ((size_t)bloc * T_ + t) * (size_t)G4 + j0 + 2 * w;
#pragma unroll
            for (int gg = 0; gg < 4; gg++)
                xg[gg] = __ldg(reinterpret_cast<const float2*>(xw + xbase + (size_t)gg * H_));
        }

        float acc0[4], acc1[4];
#pragma unroll
        for (int e = 0; e < 4; e++) { acc0[e] = 0.f; acc1[e] = 0.f; }

#define LSTM_MMA_CHUNK(C, WAITN)                                                   \
        {                                                                          \
            cp_wait_n<WAITN>();                                                    \
            __syncthreads();                                                       \
            _Pragma("unroll")                                                      \
            for (int ks = 0; ks < 16; ks++) {                                      \
                int kk = (C) * 256 + ks * 16;                                      \
                uint32_t bfr[2];                                                   \
                ldmatrix_x2t(bfr, U_u + ((kk + (lane & 15)) * 72 + w * 8) * 2);    \
                uint32_t a0[4], a1[4];                                             \
                ldmatrix_x4(a0, A_u + (((lane & 15)) * 1032                        \
                                       + kk + (lane >> 4) * 8) * 2);               \
                ldmatrix_x4(a1, A_u + ((16 + (lane & 15)) * 1032                   \
                                       + kk + (lane >> 4) * 8) * 2);               \
                mma16816(acc0, a0, bfr);                                           \
                mma16816(acc1, a1, bfr);                                           \
            }                                                                      \
        }
        LSTM_MMA_CHUNK(0, 3)
        LSTM_MMA_CHUNK(1, 2)
        LSTM_MMA_CHUNK(2, 1)
        LSTM_MMA_CHUNK(3, 0)
#undef LSTM_MMA_CHUNK

        __syncthreads();   // all warps done reading A_s; red alias now safe

        // warp-private gate transpose: redw[row][col], col = 2*gate + jj
        {
            const int g_ = lane >> 2, t4 = lane & 3;
            redw[(g_)      * 10 + 2 * t4]     = acc0[0];
            redw[(g_)      * 10 + 2 * t4 + 1] = acc0[1];
            redw[(g_ + 8)  * 10 + 2 * t4]     = acc0[2];
            redw[(g_ + 8)  * 10 + 2 * t4 + 1] = acc0[3];
            redw[(g_ + 16) * 10 + 2 * t4]     = acc1[0];
            redw[(g_ + 16) * 10 + 2 * t4 + 1] = acc1[1];
            redw[(g_ + 24) * 10 + 2 * t4]     = acc1[2];
            redw[(g_ + 24) * 10 + 2 * t4 + 1] = acc1[3];
        }
        __syncwarp();

        // cell update: lane handles row=lane, both j
        {
            float iva = redw[lane * 10 + 0] + xg[0].x;
            float ivb = redw[lane * 10 + 1] + xg[0].y;
            float fva = redw[lane * 10 + 2] + xg[1].x;
            float fvb = redw[lane * 10 + 3] + xg[1].y;
            float gva = redw[lane * 10 + 4] + xg[2].x;
            float gvb = redw[lane * 10 + 5] + xg[2].y;
            float ova = redw[lane * 10 + 6] + xg[3].x;
            float ovb = redw[lane * 10 + 7] + xg[3].y;

            float cna = sigmoidf_(fva) * creg.x + sigmoidf_(iva) * tanhf(gva);
            float cnb = sigmoidf_(fvb) * creg.y + sigmoidf_(ivb) * tanhf(gvb);
            float hna = sigmoidf_(ova) * tanhf(cna);
            float hnb = sigmoidf_(ovb) * tanhf(cnb);
            creg.x = cna; creg.y = cnb;

            __half2 h2 = __floats2half2_rn(hna, hnb);
            *reinterpret_cast<__half2*>(h16 + (size_t)bloc * H_ + j0 + 2 * w) = h2;
            *reinterpret_cast<__half2*>(
                ys16 + ((size_t)bloc * T_ + t) * (size_t)H_ + j0 + 2 * w) = h2;
        }
        grid_barrier(gridDim.x);
    }

    // write back final cell state
    *reinterpret_cast<float2*>(cout + (size_t)bloc * H_ + j0 + 2 * w) = creg;
}

// ---------------------------------------------------------------------------
// fc2 split-K: z2(64,36) += z1(64,131072) @ W(131072,36); z2 pre-seeded w/ bias
// 512 blocks, each owns a K-chunk of 256; A and W staged in SMEM.
// ---------------------------------------------------------------------------
constexpr int FC2_SMEM = 256 * 65 * 4 + 256 * 37 * 4;  // 104448

__global__ void __launch_bounds__(256) fc2_split(
    const float* __restrict__ z1, const float* __restrict__ W,
    float* __restrict__ z2)
{
    extern __shared__ float smf[];
    float* As = smf;                 // [256 k][65 m-pad]
    float* Ws = smf + 256 * 65;      // [256 k][37 n-pad]
    const int k0 = blockIdx.x * 256;
    const int tid = threadIdx.x;

    for (int i = 0; i < 16; i++) {
        int idx = tid + i * 256;
        int m = idx >> 6, kc = (idx & 63) * 4;
        float4 v = *reinterpret_cast<const float4*>(z1 + (size_t)m * 131072 + k0 + kc);
        As[(kc + 0) * 65 + m] = v.x;
        As[(kc + 1) * 65 + m] = v.y;
        As[(kc + 2) * 65 + m] = v.z;
        As[(kc + 3) * 65 + m] = v.w;
    }
    for (int i = 0; i < 36; i++) {
        int idx = tid + i * 256;
        int k = idx / 36, n = idx - k * 36;
        Ws[k * 37 + n] = W[(size_t)(k0 + k) * 36 + n];
    }
    __syncthreads();

    const int m = tid & 63, ng = tid >> 6;
    const int n0 = ng * 9;
    float acc[9];
#pragma unroll
    for (int j = 0; j < 9; j++) acc[j] = 0.f;

    for (int k = 0; k < 256; k++) {
        float a = As[k * 65 + m];
#pragma unroll
        for (int j = 0; j < 9; j++) acc[j] = fmaf(a, Ws[k * 37 + n0 + j], acc[j]);
    }
#pragma unroll
    for (int j = 0; j < 9; j++) atomicAdd(&z2[m * 36 + n0 + j], acc[j]);
}

__global__ void z2_init(const float* __restrict__ bias, float* __restrict__ z2)
{
    int i = blockIdx.x * 256 + threadIdx.x;
    if (i < B_ * 36) z2[i] = bias[i % 36];
}

// fc3 (36->6) + fc4 (6->6) + relu
__global__ void fc34_kernel(const float* __restrict__ z2,
                            const float* __restrict__ w3, const float* __restrict__ b3,
                            const float* __restrict__ w4, const float* __restrict__ b4,
                            float* __restrict__ out)
{
    int m = threadIdx.x;
    if (m >= B_) return;
    float t3[6];
#pragma unroll
    for (int n = 0; n < 6; n++) {
        float s = b3[n];
        for (int k = 0; k < 36; k++) s = fmaf(z2[m * 36 + k], w3[k * 6 + n], s);
        t3[n] = s;
    }
#pragma unroll
    for (int n = 0; n < 6; n++) {
        float s = b4[n];
#pragma unroll
        for (int k = 0; k < 6; k++) s = fmaf(t3[k], w4[k * 6 + n], s);
        out[m * 6 + n] = fmaxf(s, 0.f);
    }
}

// ---------------------------------------------------------------------------
extern "C" void kernel_launch(void* const* d_in, const int* in_sizes, int n_in,
                              void* d_out, int out_size)
{
    const float* x     = (const float*)d_in[0];
    const float* h0    = (const float*)d_in[1];
    const float* c0    = (const float*)d_in[2];
    const float* W1    = (const float*)d_in[3];
    const float* U1    = (const float*)d_in[4];
    const float* b1    = (const float*)d_in[5];
    const float* W2    = (const float*)d_in[6];
    const float* U2    = (const float*)d_in[7];
    const float* b2    = (const float*)d_in[8];
    const float* fc1_w = (const float*)d_in[9];
    const float* fc1_b = (const float*)d_in[10];
    const float* fc2_w = (const float*)d_in[11];
    const float* fc2_b = (const float*)d_in[12];
    const float* fc3_w = (const float*)d_in[13];
    const float* fc3_b = (const float*)d_in[14];
    const float* fc4_w = (const float*)d_in[15];
    const float* fc4_b = (const float*)d_in[16];
    float* out = (float*)d_out;

    float *xw, *c, *z1, *z2;
    __half *h16, *x16, *W1_16, *U1_16, *W2_16, *U2_16, *fc1w16, *ys1_16, *ys2_16;
    cudaGetSymbolAddress((void**)&xw, g_xw);
    cudaGetSymbolAddress((void**)&c, g_c);
    cudaGetSymbolAddress((void**)&h16, g_h16);
    cudaGetSymbolAddress((void**)&x16, g_x16);
    cudaGetSymbolAddress((void**)&W1_16, g_W1_16);
    cudaGetSymbolAddress((void**)&U1_16, g_U1_16);
    cudaGetSymbolAddress((void**)&W2_16, g_W2_16);
    cudaGetSymbolAddress((void**)&U2_16, g_U2_16);
    cudaGetSymbolAddress((void**)&fc1w16, g_fc1w16);
    cudaGetSymbolAddress((void**)&ys1_16, g_ys1_16);
    cudaGetSymbolAddress((void**)&ys2_16, g_ys2_16);
    cudaGetSymbolAddress((void**)&z1, g_z1);
    cudaGetSymbolAddress((void**)&z2, g_z2);

    static bool attr_done = false;
    if (!attr_done) {
        cudaFuncSetAttribute(lstm_layer_tc2,
                             cudaFuncAttributeMaxDynamicSharedMemorySize, LSTM_SMEM);
        cudaFuncSetAttribute(fc2_split,
                             cudaFuncAttributeMaxDynamicSharedMemorySize, FC2_SMEM);
        attr_done = true;
    }

    const int MT = B_ * T_;  // 16384

    auto conv = [](const float* src, __half* dst, int n) {
        f32_to_f16<<<(n / 4 + 255) / 256, 256>>>(src, dst, n);
    };
    conv(x, x16, MT * D_);
    conv(W1, W1_16, D_ * G4);
    conv(U1, U1_16, H_ * G4);
    conv(W2, W2_16, H_ * G4);
    conv(U2, U2_16, H_ * G4);
    conv(fc1_w, fc1w16, H_ * (H_ / 2));
    init_h16<<<BH / 256, 256>>>(h0, h16);

    // xw = x @ W1 + b1
    hgemm<<<dim3(G4 / 128, MT / 128), 256>>>(x16, W1_16, b1, xw, MT, G4, D_);

    // LSTM layer 1 (c seeded from c0, final c -> g_c)
    lstm_layer_tc2<<<128, 256, LSTM_SMEM>>>(U1_16, xw, c0, c, h16, ys1_16);

    // xw = ys1 @ W2 + b2
    hgemm<<<dim3(G4 / 128, MT / 128), 256>>>(ys1_16, W2_16, b2, xw, MT, G4, H_);

    // LSTM layer 2 (h16/c carry over from layer 1 — matches reference seeding)
    lstm_layer_tc2<<<128, 256, LSTM_SMEM>>>(U2_16, xw, c, c, h16, ys2_16);

    // z1 = ys2 @ fc1_w + fc1_b
    hgemm<<<dim3((H_ / 2) / 128, MT / 128), 256>>>(ys2_16, fc1w16, fc1_b, z1,
                                                   MT, H_ / 2, H_);

    // fc2: z2 = bias, then split-K accumulate
    z2_init<<<(B_ * 36 + 255) / 256, 256>>>(fc2_b, z2);
    fc2_split<<<512, 256, FC2_SMEM>>>(z1, fc2_w, z2);

    // fc3 + fc4 + relu -> out (64, 6)
    fc34_kernel<<<1, 64>>>(z2, fc3_w, fc3_b, fc4_w, fc4_b, out);
}

// round 8
// speedup vs baseline: 7.3564x; 1.0593x over previous
#include <cuda_runtime.h>
#include <cuda_fp16.h>
#include <math.h>
#include <stdint.h>

// Problem constants
constexpr int B_ = 64;
constexpr int T_ = 256;
constexpr int D_ = 512;
constexpr int H_ = 1024;
constexpr int G4 = 4 * H_;         // 4096
constexpr int BH = B_ * H_;        // 65536

// ------------------------- device scratch (no allocs) ----------------------
__device__ float  g_xw[(size_t)B_ * T_ * G4];        // (B*T, 4H) fp32
__device__ float  g_c[BH];                           // cell state fp32
__device__ __half g_h16[2 * BH];                     // double-buffered hidden
__device__ __half g_x16[(size_t)B_ * T_ * D_];
__device__ __half g_W1_16[(size_t)D_ * G4];
__device__ __half g_U1_16[(size_t)H_ * G4];
__device__ __half g_W2_16[(size_t)H_ * G4];
__device__ __half g_U2_16[(size_t)H_ * G4];
__device__ __half g_fc1w16[(size_t)H_ * (H_ / 2)];
__device__ __half g_ys1_16[(size_t)B_ * T_ * H_];
__device__ __half g_ys2_16[(size_t)B_ * T_ * H_];
__device__ float  g_z1[(size_t)B_ * T_ * (H_ / 2)];
__device__ float  g_z2[B_ * 36];
__device__ int    g_cnt[T_ * 2];                     // per-(step,bh) arrivals

// ------------------------------ PTX helpers --------------------------------
__device__ __forceinline__ uint32_t smem_u32(const void* p) {
    uint32_t a;
    asm("{ .reg .u64 t; cvta.to.shared.u64 t, %1; cvt.u32.u64 %0, t; }"
        : "=r"(a) : "l"(p));
    return a;
}
__device__ __forceinline__ void cp_async16(uint32_t dst, const void* src) {
    asm volatile("cp.async.cg.shared.global [%0], [%1], 16;" :: "r"(dst), "l"(src));
}
__device__ __forceinline__ void cp_commit() {
    asm volatile("cp.async.commit_group;");
}
template <int N> __device__ __forceinline__ void cp_wait_n() {
    asm volatile("cp.async.wait_group %0;" :: "n"(N));
}
__device__ __forceinline__ void ldmatrix_x4(uint32_t* r, uint32_t addr) {
    asm volatile("ldmatrix.sync.aligned.m8n8.x4.shared.b16 {%0,%1,%2,%3}, [%4];"
                 : "=r"(r[0]), "=r"(r[1]), "=r"(r[2]), "=r"(r[3]) : "r"(addr));
}
__device__ __forceinline__ void ldmatrix_x4t(uint32_t* r, uint32_t addr) {
    asm volatile("ldmatrix.sync.aligned.m8n8.x4.trans.shared.b16 {%0,%1,%2,%3}, [%4];"
                 : "=r"(r[0]), "=r"(r[1]), "=r"(r[2]), "=r"(r[3]) : "r"(addr));
}
__device__ __forceinline__ void ldmatrix_x2t(uint32_t* r, uint32_t addr) {
    asm volatile("ldmatrix.sync.aligned.m8n8.x2.trans.shared.b16 {%0,%1}, [%2];"
                 : "=r"(r[0]), "=r"(r[1]) : "r"(addr));
}
__device__ __forceinline__ void mma16816(float* d, const uint32_t* a, const uint32_t* b) {
    asm volatile(
        "mma.sync.aligned.m16n8k16.row.col.f32.f16.f16.f32 "
        "{%0,%1,%2,%3},{%4,%5,%6,%7},{%8,%9},{%0,%1,%2,%3};"
        : "+f"(d[0]), "+f"(d[1]), "+f"(d[2]), "+f"(d[3])
        : "r"(a[0]), "r"(a[1]), "r"(a[2]), "r"(a[3]), "r"(b[0]), "r"(b[1]));
}
// acquire load (cannot be hoisted or deleted — volatile asm)
__device__ __forceinline__ int ld_acquire_gpu(const int* p) {
    int v;
    asm volatile("ld.acquire.gpu.global.s32 %0, [%1];" : "=r"(v) : "l"(p) : "memory");
    return v;
}
// release reduction
__device__ __forceinline__ void red_release_add(int* p, int v) {
    asm volatile("red.release.gpu.global.add.s32 [%0], %1;" :: "l"(p), "r"(v) : "memory");
}

__device__ __forceinline__ float sigmoidf_(float x) { return 1.f / (1.f + expf(-x)); }

// ---------------------------------------------------------------------------
__global__ void f32_to_f16(const float* __restrict__ in, __half* __restrict__ out, int n)
{
    int i4 = (blockIdx.x * 256 + threadIdx.x) * 4;
    if (i4 < n) {
        float4 v = *reinterpret_cast<const float4*>(in + i4);
        *reinterpret_cast<__half2*>(out + i4)     = __floats2half2_rn(v.x, v.y);
        *reinterpret_cast<__half2*>(out + i4 + 2) = __floats2half2_rn(v.z, v.w);
    }
}

__global__ void init_h16(const float* __restrict__ h0, __half* __restrict__ h16)
{
    int i = blockIdx.x * 256 + threadIdx.x;
    if (i < BH) h16[i] = __float2half_rn(h0[i]);   // seed buffer 0
}

__global__ void reset_cnt(int* cnt)
{
    int i = blockIdx.x * 256 + threadIdx.x;
    if (i < T_ * 2) cnt[i] = 0;
}

// ---------------------------------------------------------------------------
// HGEMM: C_fp32(M,N) = A_fp16(M,K) @ B_fp16(K,N) + bias(N)
// 128x128x32 tile, 256 threads, double-buffered cp.async.
// ---------------------------------------------------------------------------
__global__ void __launch_bounds__(256) hgemm(
    const __half* __restrict__ A, const __half* __restrict__ Bm,
    const float* __restrict__ bias, float* __restrict__ C,
    int M, int N, int K)
{
    __shared__ __half As[2][128 * 40];
    __shared__ __half Bs[2][32 * 136];

    const int tid = threadIdx.x;
    const int w = tid >> 5, lane = tid & 31;
    const int bm = blockIdx.y * 128, bn = blockIdx.x * 128;
    const int wm = (w >> 2) * 64, wn = (w & 3) * 32;
    const uint32_t AsU = smem_u32(As), BsU = smem_u32(Bs);

    float acc[4][4][4];
#pragma unroll
    for (int i = 0; i < 4; i++)
#pragma unroll
        for (int j = 0; j < 4; j++)
#pragma unroll
            for (int e = 0; e < 4; e++) acc[i][j][e] = 0.f;

    const int nk = K / 32;

#define LOAD_TILE(kt, buf)                                                        \
    {                                                                             \
        int k0 = (kt) * 32;                                                       \
        _Pragma("unroll")                                                         \
        for (int e = 0; e < 2; e++) {                                             \
            int idx = tid + e * 256;                                              \
            int r = idx >> 2, ch = idx & 3;                                       \
            cp_async16(AsU + ((buf) * 5120 + r * 40 + ch * 8) * 2,                \
                       A + (size_t)(bm + r) * K + k0 + ch * 8);                   \
        }                                                                         \
        _Pragma("unroll")                                                         \
        for (int e = 0; e < 2; e++) {                                             \
            int idx = tid + e * 256;                                              \
            int r = idx >> 4, ch = idx & 15;                                      \
            cp_async16(BsU + ((buf) * 4352 + r * 136 + ch * 8) * 2,               \
                       Bm + (size_t)(k0 + r) * N + bn + ch * 8);                  \
        }                                                                         \
        cp_commit();                                                              \
    }

    LOAD_TILE(0, 0)
    cp_wait_n<0>();
    __syncthreads();

    for (int kt = 0; kt < nk; kt++) {
        int buf = kt & 1;
        if (kt + 1 < nk) LOAD_TILE(kt + 1, buf ^ 1)

#pragma unroll
        for (int ks = 0; ks < 2; ks++) {
            uint32_t bfr[4][2];
#pragma unroll
            for (int nf = 0; nf < 4; nf++)
                ldmatrix_x2t(bfr[nf],
                    BsU + (buf * 4352 + (ks * 16 + (lane & 15)) * 136 + wn + nf * 8) * 2);
#pragma unroll
            for (int mf = 0; mf < 4; mf++) {
                uint32_t afr[4];
                ldmatrix_x4(afr,
                    AsU + (buf * 5120 + (wm + mf * 16 + (lane & 15)) * 40
                           + ks * 16 + ((lane >> 4) * 8)) * 2);
#pragma unroll
                for (int nf = 0; nf < 4; nf++) mma16816(acc[mf][nf], afr, bfr[nf]);
            }
        }
        if (kt + 1 < nk) cp_wait_n<0>();
        __syncthreads();
    }
#undef LOAD_TILE

    const int g = lane >> 2, t4 = lane & 3;
#pragma unroll
    for (int mf = 0; mf < 4; mf++)
#pragma unroll
        for (int nf = 0; nf < 4; nf++) {
            int row0 = bm + wm + mf * 16 + g;
            int col = bn + wn + nf * 8 + t4 * 2;
            float b0 = bias ? bias[col] : 0.f;
            float b1 = bias ? bias[col + 1] : 0.f;
            C[(size_t)row0 * N + col]           = acc[mf][nf][0] + b0;
            C[(size_t)row0 * N + col + 1]       = acc[mf][nf][1] + b1;
            C[(size_t)(row0 + 8) * N + col]     = acc[mf][nf][2] + b0;
            C[(size_t)(row0 + 8) * N + col + 1] = acc[mf][nf][3] + b1;
        }
}

// ---------------------------------------------------------------------------
// Persistent tensor-core LSTM v3b. 128 CTAs = 64 j-groups x 2 batch halves.
//  - h double-buffered: read buf t&1, write buf (t+1)&1.
//  - one-sided sync with PROPER semantics: every thread __threadfence()s its
//    own h store, __syncthreads, tid0 red.release; consumers spin on
//    ld.acquire.gpu (volatile asm — compiler cannot hoist/delete the loop).
//    WAR-safe: observing cnt[t-1]==64 implies all same-bh CTAs completed
//    their step-(t-1) staging reads of the buffer overwritten at step t.
// ---------------------------------------------------------------------------
constexpr int U_BYTES   = 1024 * 72 * 2;   // 147456
constexpr int A_BYTES   = 32 * 1032 * 2;   // 66048
constexpr int LSTM_SMEM = U_BYTES + A_BYTES;  // 213504

__global__ void __launch_bounds__(256) lstm_layer_tc3(
    const __half* __restrict__ U16,   // (1024, 4096) fp16
    const float* __restrict__ xw,     // (B*T, 4096) fp32, rows b*T+t
    const float* __restrict__ cseed,  // (B,1024) fp32 initial cell
    float* __restrict__ cout,         // (B,1024) fp32 final cell
    __half* __restrict__ h16,         // [2][B][1024] fp16 (buf0 pre-seeded)
    __half* __restrict__ ys16,        // (B*T, 1024) fp16 out
    int* __restrict__ cnt)            // [T][2] arrival counters (zeroed)
{
    extern __shared__ char sm[];
    __half* U_s = (__half*)sm;                 // [1024][72]
    __half* A_s = (__half*)(sm + U_BYTES);     // [32][1032]
    float*  red = (float*)(sm + U_BYTES);      // alias: per-warp [32][10] fp32
    const uint32_t U_u = smem_u32(U_s);
    const uint32_t A_u = smem_u32(A_s);

    const int tid = threadIdx.x;
    const int w = tid >> 5, lane = tid & 31;
    const int jg = blockIdx.x >> 1;            // 0..63
    const int bh = blockIdx.x & 1;             // batch half
    const int j0 = jg * 16;

    // ---- preload U slice: U_s[k][w*8 + 2*gate + jj] = U16[k][gate*H + j0 + 2w + jj]
    for (int i = 0; i < 128; i++) {
        int idx = tid + i * 256;
        int k = idx >> 5;
        int gate = (idx >> 3) & 3;
        int ww = idx & 7;
        *reinterpret_cast<__half2*>(U_s + k * 72 + ww * 8 + 2 * gate) =
            *reinterpret_cast<const __half2*>(U16 + (size_t)k * G4 + gate * H_ + j0 + 2 * ww);
    }
    __syncthreads();

    const int bloc = bh * 32 + lane;
    float2 creg = *reinterpret_cast<const float2*>(cseed + (size_t)bloc * H_ + j0 + 2 * w);

    float* redw = red + w * 320;               // [32][10]

    for (int t = 0; t < T_; t++) {
        // prefetch xw for this lane's two cells (independent of h)
        float2 xg[4];
        {
            size_t xbase = ((size_t)bloc * T_ + t) * (size_t)G4 + j0 + 2 * w;
#pragma unroll
            for (int gg = 0; gg < 4; gg++)
                xg[gg] = __ldg(reinterpret_cast<const float2*>(xw + xbase + (size_t)gg * H_));
        }

        // wait for h[t-1] producers of our batch half (acquire spin)
        if (t > 0) {
            const int* cp = &cnt[(t - 1) * 2 + bh];
            while ((unsigned)ld_acquire_gpu(cp) < 64u) { }
        }

        const __half* hg = h16 + (size_t)(t & 1) * BH + (size_t)bh * 32 * H_;

        // issue all 4 h-staging chunks (256 cols each)
#pragma unroll
        for (int cch = 0; cch < 4; cch++) {
#pragma unroll
            for (int e = 0; e < 4; e++) {
                int idx = tid + e * 256;
                int r = idx >> 5, ch = idx & 31;
                cp_async16(A_u + (r * 1032 + cch * 256 + ch * 8) * 2,
                           hg + (size_t)r * H_ + cch * 256 + ch * 8);
            }
            cp_commit();
        }

        float acc0[4], acc1[4];
#pragma unroll
        for (int e = 0; e < 4; e++) { acc0[e] = 0.f; acc1[e] = 0.f; }

#define LSTM_MMA_CHUNK(C, WAITN)                                                   \
        {                                                                          \
            cp_wait_n<WAITN>();                                                    \
            __syncthreads();                                                       \
            _Pragma("unroll")                                                      \
            for (int ks2 = 0; ks2 < 8; ks2++) {                                    \
                int kk = (C) * 256 + ks2 * 32;                                     \
                uint32_t bq[4];                                                    \
                ldmatrix_x4t(bq, U_u + ((kk + lane) * 72 + w * 8) * 2);            \
                uint32_t a0[4], a1[4];                                             \
                ldmatrix_x4(a0, A_u + (((lane & 15)) * 1032                        \
                                       + kk + (lane >> 4) * 8) * 2);               \
                ldmatrix_x4(a1, A_u + ((16 + (lane & 15)) * 1032                   \
                                       + kk + (lane >> 4) * 8) * 2);               \
                mma16816(acc0, a0, bq);                                            \
                mma16816(acc1, a1, bq);                                            \
                uint32_t a2[4], a3[4];                                             \
                ldmatrix_x4(a2, A_u + (((lane & 15)) * 1032                        \
                                       + kk + 16 + (lane >> 4) * 8) * 2);          \
                ldmatrix_x4(a3, A_u + ((16 + (lane & 15)) * 1032                   \
                                       + kk + 16 + (lane >> 4) * 8) * 2);          \
                mma16816(acc0, a2, bq + 2);                                        \
                mma16816(acc1, a3, bq + 2);                                        \
            }                                                                      \
        }
        LSTM_MMA_CHUNK(0, 3)
        LSTM_MMA_CHUNK(1, 2)
        LSTM_MMA_CHUNK(2, 1)
        LSTM_MMA_CHUNK(3, 0)
#undef LSTM_MMA_CHUNK

        __syncthreads();   // all warps done reading A_s; red alias now safe

        // warp-private gate transpose: redw[row][col], col = 2*gate + jj
        {
            const int g_ = lane >> 2, t4 = lane & 3;
            redw[(g_)      * 10 + 2 * t4]     = acc0[0];
            redw[(g_)      * 10 + 2 * t4 + 1] = acc0[1];
            redw[(g_ + 8)  * 10 + 2 * t4]     = acc0[2];
            redw[(g_ + 8)  * 10 + 2 * t4 + 1] = acc0[3];
            redw[(g_ + 16) * 10 + 2 * t4]     = acc1[0];
            redw[(g_ + 16) * 10 + 2 * t4 + 1] = acc1[1];
            redw[(g_ + 24) * 10 + 2 * t4]     = acc1[2];
            redw[(g_ + 24) * 10 + 2 * t4 + 1] = acc1[3];
        }
        __syncwarp();

        // cell update: lane handles row=lane (bloc), both j
        {
            float iva = redw[lane * 10 + 0] + xg[0].x;
            float ivb = redw[lane * 10 + 1] + xg[0].y;
            float fva = redw[lane * 10 + 2] + xg[1].x;
            float fvb = redw[lane * 10 + 3] + xg[1].y;
            float gva = redw[lane * 10 + 4] + xg[2].x;
            float gvb = redw[lane * 10 + 5] + xg[2].y;
            float ova = redw[lane * 10 + 6] + xg[3].x;
            float ovb = redw[lane * 10 + 7] + xg[3].y;

            float cna = sigmoidf_(fva) * creg.x + sigmoidf_(iva) * tanhf(gva);
            float cnb = sigmoidf_(fvb) * creg.y + sigmoidf_(ivb) * tanhf(gvb);
            float hna = sigmoidf_(ova) * tanhf(cna);
            float hnb = sigmoidf_(ovb) * tanhf(cnb);
            creg.x = cna; creg.y = cnb;

            __half2 h2 = __floats2half2_rn(hna, hnb);
            *reinterpret_cast<__half2*>(
                h16 + (size_t)((t + 1) & 1) * BH + (size_t)bloc * H_ + j0 + 2 * w) = h2;
            *reinterpret_cast<__half2*>(
                ys16 + ((size_t)bloc * T_ + t) * (size_t)H_ + j0 + 2 * w) = h2;
        }

        // release: EVERY thread fences its own store, then tid0 release-adds
        __threadfence();
        __syncthreads();
        if (tid == 0) red_release_add(&cnt[t * 2 + bh], 1);
    }

    // write back final cell state
    *reinterpret_cast<float2*>(cout + (size_t)bloc * H_ + j0 + 2 * w) = creg;
}

// ---------------------------------------------------------------------------
// fc2 split-K: z2(64,36) += z1(64,131072) @ W(131072,36); z2 pre-seeded w/ bias
// ---------------------------------------------------------------------------
constexpr int FC2_SMEM = 256 * 65 * 4 + 256 * 37 * 4;  // 104448

__global__ void __launch_bounds__(256) fc2_split(
    const float* __restrict__ z1, const float* __restrict__ W,
    float* __restrict__ z2)
{
    extern __shared__ float smf[];
    float* As = smf;                 // [256 k][65 m-pad]
    float* Ws = smf + 256 * 65;      // [256 k][37 n-pad]
    const int k0 = blockIdx.x * 256;
    const int tid = threadIdx.x;

    for (int i = 0; i < 16; i++) {
        int idx = tid + i * 256;
        int m = idx >> 6, kc = (idx & 63) * 4;
        float4 v = *reinterpret_cast<const float4*>(z1 + (size_t)m * 131072 + k0 + kc);
        As[(kc + 0) * 65 + m] = v.x;
        As[(kc + 1) * 65 + m] = v.y;
        As[(kc + 2) * 65 + m] = v.z;
        As[(kc + 3) * 65 + m] = v.w;
    }
    for (int i = 0; i < 36; i++) {
        int idx = tid + i * 256;
        int k = idx / 36, n = idx - k * 36;
        Ws[k * 37 + n] = W[(size_t)(k0 + k) * 36 + n];
    }
    __syncthreads();

    const int m = tid & 63, ng = tid >> 6;
    const int n0 = ng * 9;
    float acc[9];
#pragma unroll
    for (int j = 0; j < 9; j++) acc[j] = 0.f;

    for (int k = 0; k < 256; k++) {
        float a = As[k * 65 + m];
#pragma unroll
        for (int j = 0; j < 9; j++) acc[j] = fmaf(a, Ws[k * 37 + n0 + j], acc[j]);
    }
#pragma unroll
    for (int j = 0; j < 9; j++) atomicAdd(&z2[m * 36 + n0 + j], acc[j]);
}

__global__ void z2_init(const float* __restrict__ bias, float* __restrict__ z2)
{
    int i = blockIdx.x * 256 + threadIdx.x;
    if (i < B_ * 36) z2[i] = bias[i % 36];
}

// fc3 (36->6) + fc4 (6->6) + relu
__global__ void fc34_kernel(const float* __restrict__ z2,
                            const float* __restrict__ w3, const float* __restrict__ b3,
                            const float* __restrict__ w4, const float* __restrict__ b4,
                            float* __restrict__ out)
{
    int m = threadIdx.x;
    if (m >= B_) return;
    float t3[6];
#pragma unroll
    for (int n = 0; n < 6; n++) {
        float s = b3[n];
        for (int k = 0; k < 36; k++) s = fmaf(z2[m * 36 + k], w3[k * 6 + n], s);
        t3[n] = s;
    }
#pragma unroll
    for (int n = 0; n < 6; n++) {
        float s = b4[n];
#pragma unroll
        for (int k = 0; k < 6; k++) s = fmaf(t3[k], w4[k * 6 + n], s);
        out[m * 6 + n] = fmaxf(s, 0.f);
    }
}

// ---------------------------------------------------------------------------
extern "C" void kernel_launch(void* const* d_in, const int* in_sizes, int n_in,
                              void* d_out, int out_size)
{
    const float* x     = (const float*)d_in[0];
    const float* h0    = (const float*)d_in[1];
    const float* c0    = (const float*)d_in[2];
    const float* W1    = (const float*)d_in[3];
    const float* U1    = (const float*)d_in[4];
    const float* b1    = (const float*)d_in[5];
    const float* W2    = (const float*)d_in[6];
    const float* U2    = (const float*)d_in[7];
    const float* b2    = (const float*)d_in[8];
    const float* fc1_w = (const float*)d_in[9];
    const float* fc1_b = (const float*)d_in[10];
    const float* fc2_w = (const float*)d_in[11];
    const float* fc2_b = (const float*)d_in[12];
    const float* fc3_w = (const float*)d_in[13];
    const float* fc3_b = (const float*)d_in[14];
    const float* fc4_w = (const float*)d_in[15];
    const float* fc4_b = (const float*)d_in[16];
    float* out = (float*)d_out;

    float *xw, *c, *z1, *z2;
    int* cnt;
    __half *h16, *x16, *W1_16, *U1_16, *W2_16, *U2_16, *fc1w16, *ys1_16, *ys2_16;
    cudaGetSymbolAddress((void**)&xw, g_xw);
    cudaGetSymbolAddress((void**)&c, g_c);
    cudaGetSymbolAddress((void**)&h16, g_h16);
    cudaGetSymbolAddress((void**)&x16, g_x16);
    cudaGetSymbolAddress((void**)&W1_16, g_W1_16);
    cudaGetSymbolAddress((void**)&U1_16, g_U1_16);
    cudaGetSymbolAddress((void**)&W2_16, g_W2_16);
    cudaGetSymbolAddress((void**)&U2_16, g_U2_16);
    cudaGetSymbolAddress((void**)&fc1w16, g_fc1w16);
    cudaGetSymbolAddress((void**)&ys1_16, g_ys1_16);
    cudaGetSymbolAddress((void**)&ys2_16, g_ys2_16);
    cudaGetSymbolAddress((void**)&z1, g_z1);
    cudaGetSymbolAddress((void**)&z2, g_z2);
    cudaGetSymbolAddress((void**)&cnt, g_cnt);

    static bool attr_done = false;
    if (!attr_done) {
        cudaFuncSetAttribute(lstm_layer_tc3,
                             cudaFuncAttributeMaxDynamicSharedMemorySize, LSTM_SMEM);
        cudaFuncSetAttribute(fc2_split,
                             cudaFuncAttributeMaxDynamicSharedMemorySize, FC2_SMEM);
        attr_done = true;
    }

    const int MT = B_ * T_;  // 16384

    auto conv = [](const float* src, __half* dst, int n) {
        f32_to_f16<<<(n / 4 + 255) / 256, 256>>>(src, dst, n);
    };
    conv(x, x16, MT * D_);
    conv(W1, W1_16, D_ * G4);
    conv(U1, U1_16, H_ * G4);
    conv(W2, W2_16, H_ * G4);
    conv(U2, U2_16, H_ * G4);
    conv(fc1_w, fc1w16, H_ * (H_ / 2));
    init_h16<<<BH / 256, 256>>>(h0, h16);

    // xw = x @ W1 + b1
    hgemm<<<dim3(G4 / 128, MT / 128), 256>>>(x16, W1_16, b1, xw, MT, G4, D_);

    // LSTM layer 1 (c seeded from c0, final c -> g_c)
    reset_cnt<<<2, 256>>>(cnt);
    lstm_layer_tc3<<<128, 256, LSTM_SMEM>>>(U1_16, xw, c0, c, h16, ys1_16, cnt);

    // xw = ys1 @ W2 + b2
    hgemm<<<dim3(G4 / 128, MT / 128), 256>>>(ys1_16, W2_16, b2, xw, MT, G4, H_);

    // LSTM layer 2 (h16 buf0 / c carry over — matches reference seeding)
    reset_cnt<<<2, 256>>>(cnt);
    lstm_layer_tc3<<<128, 256, LSTM_SMEM>>>(U2_16, xw, c, c, h16, ys2_16, cnt);

    // z1 = ys2 @ fc1_w + fc1_b
    hgemm<<<dim3((H_ / 2) / 128, MT / 128), 256>>>(ys2_16, fc1w16, fc1_b, z1,
                                                   MT, H_ / 2, H_);

    // fc2: z2 = bias, then split-K accumulate
    z2_init<<<(B_ * 36 + 255) / 256, 256>>>(fc2_b, z2);
    fc2_split<<<512, 256, FC2_SMEM>>>(z1, fc2_w, z2);

    // fc3 + fc4 + relu -> out (64, 6)
    fc34_kernel<<<1, 64>>>(z2, fc3_w, fc3_b, fc4_w, fc4_b, out);
}